// round 8
// baseline (speedup 1.0000x reference)
#include <cuda_runtime.h>
#include <cuda_bf16.h>

// Problem constants (fixed by setup_inputs)
constexpr int B  = 8;
constexpr int N  = 16384;
constexpr int G  = 128;
constexpr int NC = 11;          // N_CLASSES
constexpr float THRESH = 0.3f;  // REG_FG_THRESH

// ---- packed f32x2 helpers (Blackwell sm_103a) ----
typedef unsigned long long ull;
__device__ __forceinline__ ull pk2(float lo, float hi) {
    ull r; asm("mov.b64 %0,{%1,%2};" : "=l"(r) : "f"(lo), "f"(hi)); return r;
}
__device__ __forceinline__ void upk2(ull v, float& lo, float& hi) {
    asm("mov.b64 {%0,%1},%2;" : "=f"(lo), "=f"(hi) : "l"(v));
}
__device__ __forceinline__ ull add2(ull a, ull b) {
    ull r; asm("add.rn.f32x2 %0,%1,%2;" : "=l"(r) : "l"(a), "l"(b)); return r;
}
__device__ __forceinline__ ull mul2(ull a, ull b) {
    ull r; asm("mul.rn.f32x2 %0,%1,%2;" : "=l"(r) : "l"(a), "l"(b)); return r;
}
__device__ __forceinline__ ull fma2(ull a, ull b, ull c) {
    ull r; asm("fma.rn.f32x2 %0,%1,%2,%3;" : "=l"(r) : "l"(a), "l"(b), "l"(c)); return r;
}

// Output layout (concatenated, float32):
//   [0,            B*N*7)   batch_rois
//   [B*N*7,        2*B*N*7) gt_of_rois
//   [2*B*N*7,      +B*N)    gt_label_of_rois (as float)
//   [2*B*N*7+B*N,  +B*N)    reg_valid_mask

__global__ __launch_bounds__(256)
void ptl_kernel(const float* __restrict__ rois,
                const float* __restrict__ gt,
                const int*   __restrict__ gt_lab,
                const float* __restrict__ assign_gt,
                const int*   __restrict__ assign_lab,
                float* __restrict__ out)
{
    // Shared GT cache for this batch.
    // Filter data, pair p covers boxes e=2p, o=2p+1:
    //   sCXY[p] = (-cx_e, -cx_o, -cy_e, -cy_o)   (one LDS.128)
    //   sCZ [2p..] = (-cz_e, -cz_o)              (one LDS.64)
    __shared__ float4 sCXY[G / 2];
    __shared__ float  sCZ[G];
    __shared__ float4 sMin[G];         // bmin.x, bmin.y, bmin.z, vol_b
    __shared__ float4 sMax[G];         // bmax.x, bmax.y, bmax.z, (pad)
    __shared__ float  sBox[G][8];      // cx cy cz dx dy dz (-h) label_bits
    __shared__ float  sRbMax[4];       // per-warp rb maxima (warps 0-3)

    const int tid   = threadIdx.x;           // 0..255
    const int batch = blockIdx.x >> 7;       // 128 blocks per batch
    const int rloc  = tid >> 1;              // ROI slot within block: 0..127
    const int half  = tid & 1;               // GT half this thread scans
    const int row   = ((blockIdx.x & 127) << 7) + rloc;

    if (tid < G) {
        // one GT box per thread (first 4 warps)
        const float* gp = gt + ((size_t)batch * G + tid) * 7;
        float cx = gp[0], cy = gp[1], cz = gp[2];
        float dx = gp[3], dy = gp[4], dz = gp[5];
        float h  = gp[6];
        sMin[tid] = make_float4(cx - 0.5f * dx, cy - 0.5f * dy, cz - 0.5f * dz,
                                dx * dy * dz);
        sMax[tid] = make_float4(cx + 0.5f * dx, cy + 0.5f * dy, cz + 0.5f * dz, 0.f);
        sBox[tid][0] = cx; sBox[tid][1] = cy; sBox[tid][2] = cz;
        sBox[tid][3] = dx; sBox[tid][4] = dy; sBox[tid][5] = dz;
        sBox[tid][6] = -h;  // heading multiplied by -1 per reference
        sBox[tid][7] = __int_as_float(gt_lab[(size_t)batch * G + tid]);

        const int p = tid >> 1, lane = tid & 1;
        float* pc = (float*)&sCXY[p];
        pc[0 + lane] = -cx;  pc[2 + lane] = -cy;
        sCZ[tid] = -cz;

        // box half-diagonal; per-warp max via shfl, cross-warp via smem
        float rb = 0.5f * sqrtf(dx * dx + dy * dy + dz * dz);
        #pragma unroll
        for (int s = 16; s; s >>= 1)
            rb = fmaxf(rb, __shfl_xor_sync(0xffffffffu, rb, s));
        if ((tid & 31) == 0) sRbMax[tid >> 5] = rb;
    }
    __syncthreads();
    const float rbmax = fmaxf(fmaxf(sRbMax[0], sRbMax[1]),
                              fmaxf(sRbMax[2], sRbMax[3]));

    const size_t ri = (size_t)batch * N + row;
    const float* rp = rois + ri * 7;   // both pair threads load (L1 hit)

    const float r0 = rp[0], r1 = rp[1], r2 = rp[2];
    const float r3 = rp[3], r4 = rp[4], r5 = rp[5];
    const float r6 = rp[6];

    const float aminx = r0 - 0.5f * r3, amaxx = r0 + 0.5f * r3;
    const float aminy = r1 - 0.5f * r4, amaxy = r1 + 0.5f * r4;
    const float aminz = r2 - 0.5f * r5, amaxz = r2 + 0.5f * r5;
    const float va = r3 * r4 * r5;
    const float ra = 0.5f * sqrtf(r3 * r3 + r4 * r4 + r5 * r5);

    // Filter constant: inter>0 => dsq < (ra+rb_g)^2 <= (ra+rbmax)^2 < C
    // (Cauchy-Schwarz). +0.5 margin absorbs all fp rounding; '<=' compare
    // keeps it conservative, so the filter is exactly lossless: zero-inter
    // pairs can never win the strict-'>' argmax.
    const float Cr = ra + rbmax + 0.5f;
    const float C  = Cr * Cr;

    const ull ax2 = pk2(r0, r0);
    const ull ay2 = pk2(r1, r1);
    const ull az2 = pk2(r2, r2);

    // ---- Phase 1: packed sphere filter over THIS thread's half (64 boxes) ----
    // chunks cc = 2*half, 2*half+1; mask bits via OR tree (independent dataflow).
    unsigned mk[2];
    #pragma unroll
    for (int c = 0; c < 2; ++c) {
        const int cc = half * 2 + c;
        unsigned t[16];
        #pragma unroll
        for (int i = 0; i < 16; ++i) {
            const int p = cc * 16 + i;
            const ulonglong2 qxy = *(const ulonglong2*)&sCXY[p];
            const ull qz = *(const ull*)&sCZ[2 * p];
            const ull dx2 = add2(ax2, qxy.x);
            const ull dy2 = add2(ay2, qxy.y);
            const ull dz2 = add2(az2, qz);
            ull s2 = mul2(dx2, dx2);
            s2 = fma2(dy2, dy2, s2);
            s2 = fma2(dz2, dz2, s2);
            float s_lo, s_hi;
            upk2(s2, s_lo, s_hi);
            t[i] = (s_lo <= C ? (1u << (2 * i)) : 0u)
                 | (s_hi <= C ? (2u << (2 * i)) : 0u);
        }
        #pragma unroll
        for (int stp = 1; stp < 16; stp <<= 1)
            #pragma unroll
            for (int i = 0; i < 16; i += 2 * stp)
                t[i] |= t[i + stp];
        mk[c] = t[0];
    }

    // ---- Phase 2: exact IoU-argmax over this half's survivors ----
    // iou = inter/(s-inter), s = va+vb, strictly monotone in inter/s
    // => argmax via cross-mult compare; strict '>' keeps first max.
    // Half-local init index = first box of this half (64*half).
    float bi = 0.f, bs = 1.f; int bg = 64 * half;
    #pragma unroll
    for (int c = 0; c < 2; ++c) {
        unsigned m = mk[c];
        while (m) {
            const int b = __ffs(m) - 1;
            m &= m - 1;
            const int g = (half * 2 + c) * 32 + b;
            const float4 mn = sMin[g];
            const float4 mx = sMax[g];
            float ox = fminf(amaxx, mx.x) - fmaxf(aminx, mn.x);
            float oy = fminf(amaxy, mx.y) - fmaxf(aminy, mn.y);
            float oz = fminf(amaxz, mx.z) - fmaxf(aminz, mn.z);
            ox = fmaxf(ox, 0.0f);
            oy = fmaxf(oy, 0.0f);
            oz = fmaxf(oz, 0.0f);
            const float inter = ox * oy * oz;
            const float s     = va + mn.w;
            if (inter * bs > bi * s) { bi = inter; bs = s; bg = g; }
        }
    }

    // ---- Pair merge via shfl (partner = lane^1) ----
    // lo = half-0 result (incumbent), hi = half-1 (challenger wins only on
    // strict '>'): exact first-max tie-break across the full 128-box range.
    {
        const float obi = __shfl_xor_sync(0xffffffffu, bi, 1);
        const float obs = __shfl_xor_sync(0xffffffffu, bs, 1);
        const int   obg = __shfl_xor_sync(0xffffffffu, bg, 1);
        float lo_bi, lo_bs, hi_bi, hi_bs; int lo_bg, hi_bg;
        if (half == 0) { lo_bi = bi;  lo_bs = bs;  lo_bg = bg;
                         hi_bi = obi; hi_bs = obs; hi_bg = obg; }
        else           { lo_bi = obi; lo_bs = obs; lo_bg = obg;
                         hi_bi = bi;  hi_bs = bs;  hi_bg = bg; }
        if (hi_bi * lo_bs > lo_bi * hi_bs) { bi = hi_bi; bs = hi_bs; bg = hi_bg; }
        else                               { bi = lo_bi; bs = lo_bs; bg = lo_bg; }
    }

    const int  alab = assign_lab[ri];
    const bool pos1 = (alab >= 0);
    // max_ov >= THRESH  <=>  bi >= THRESH * clip(s - bi, 1e-6)
    const bool pos2 = (!pos1) && (bi >= THRESH * fmaxf(bs - bi, 1e-6f));

    float* o_rois = out;
    float* o_gt   = out + (size_t)B * N * 7;
    float* o_lab  = out + (size_t)B * N * 14;
    float* o_mask = o_lab + (size_t)B * N;

    if (half == 0) {
        // rois passthrough + label + mask
        o_rois[ri * 7 + 0] = r0; o_rois[ri * 7 + 1] = r1; o_rois[ri * 7 + 2] = r2;
        o_rois[ri * 7 + 3] = r3; o_rois[ri * 7 + 4] = r4; o_rois[ri * 7 + 5] = r5;
        o_rois[ri * 7 + 6] = r6;
        int lab = pos1 ? alab : (pos2 ? __float_as_int(sBox[bg][7]) : NC);
        o_lab[ri]  = (float)lab;
        o_mask[ri] = (pos1 || pos2) ? 1.0f : 0.0f;
    } else {
        const float* ag = assign_gt + ri * 7;
        #pragma unroll
        for (int k = 0; k < 7; ++k) {
            float gv;
            if (pos1) {
                gv = ag[k];
                if (k == 6) gv = -gv;   // assign_gt heading negated per reference
            } else if (pos2) {
                gv = sBox[bg][k];       // heading already negated at store time
            } else {
                gv = 0.0f;              // must write: d_out is poisoned
            }
            o_gt[ri * 7 + k] = gv;
        }
    }
}

extern "C" void kernel_launch(void* const* d_in, const int* in_sizes, int n_in,
                              void* d_out, int out_size)
{
    const float* rois       = (const float*)d_in[0]; // [B,N,7]
    const float* gt         = (const float*)d_in[1]; // [B,G,7]
    const int*   gt_lab     = (const int*)  d_in[2]; // [B,G]
    const float* assign_gt  = (const float*)d_in[3]; // [B,N,7]
    const int*   assign_lab = (const int*)  d_in[4]; // [B,N]
    float*       out        = (float*)d_out;

    // 2 threads per ROI: 256 threads/block covers 128 ROIs; 128 blocks/batch
    ptl_kernel<<<(B * N) / 128, 256>>>(rois, gt, gt_lab, assign_gt, assign_lab, out);
}

// round 9
// speedup vs baseline: 1.2885x; 1.2885x over previous
#include <cuda_runtime.h>
#include <cuda_bf16.h>

// Problem constants (fixed by setup_inputs)
constexpr int B  = 8;
constexpr int N  = 16384;
constexpr int G  = 128;
constexpr int NC = 11;          // N_CLASSES
constexpr float THRESH = 0.3f;  // REG_FG_THRESH
constexpr int BLK = 128;
constexpr int F4_PER_REGION = BLK * 7 / 4;   // 224 float4 per 128-row x 7 region

// ---- packed f32x2 helpers (Blackwell sm_103a) ----
typedef unsigned long long ull;
__device__ __forceinline__ ull pk2(float lo, float hi) {
    ull r; asm("mov.b64 %0,{%1,%2};" : "=l"(r) : "f"(lo), "f"(hi)); return r;
}
__device__ __forceinline__ void upk2(ull v, float& lo, float& hi) {
    asm("mov.b64 {%0,%1},%2;" : "=f"(lo), "=f"(hi) : "l"(v));
}
__device__ __forceinline__ ull add2(ull a, ull b) {
    ull r; asm("add.rn.f32x2 %0,%1,%2;" : "=l"(r) : "l"(a), "l"(b)); return r;
}
__device__ __forceinline__ ull mul2(ull a, ull b) {
    ull r; asm("mul.rn.f32x2 %0,%1,%2;" : "=l"(r) : "l"(a), "l"(b)); return r;
}
__device__ __forceinline__ ull fma2(ull a, ull b, ull c) {
    ull r; asm("fma.rn.f32x2 %0,%1,%2,%3;" : "=l"(r) : "l"(a), "l"(b), "l"(c)); return r;
}

// Output layout (concatenated, float32):
//   [0,            B*N*7)   batch_rois
//   [B*N*7,        2*B*N*7) gt_of_rois
//   [2*B*N*7,      +B*N)    gt_label_of_rois (as float)
//   [2*B*N*7+B*N,  +B*N)    reg_valid_mask

__global__ __launch_bounds__(BLK)
void ptl_kernel(const float* __restrict__ rois,
                const float* __restrict__ gt,
                const int*   __restrict__ gt_lab,
                const float* __restrict__ assign_gt,
                const int*   __restrict__ assign_lab,
                float* __restrict__ out)
{
    // GT tables
    __shared__ float4 sCXY[G / 2];     // (-cx_e,-cx_o,-cy_e,-cy_o) per pair
    __shared__ float  sCZ[G];          // -cz, pair-adjacent -> u64 view
    __shared__ float4 sMin[G];         // bmin.xyz, vol_b
    __shared__ float4 sMax[G];         // bmax.xyz, pad
    __shared__ float  sBox[G][8];      // cx cy cz dx dy dz (-h) label_bits
    __shared__ float  sRbMax[4];
    // Staging buffers (row r occupies [r*7, r*7+7); stride 7 coprime to 32
    // -> conflict-free scalar LDS/STS per row)
    __shared__ alignas(16) float sGT[BLK * 7];   // gt in -> gt_of_rois out
    __shared__ alignas(16) float sRO[BLK * 7];   // rois in -> rois passthrough out
    __shared__ alignas(16) float sAG[BLK * 7];   // assign_gt in
    __shared__ alignas(16) float sL[BLK];        // label out
    __shared__ alignas(16) float sM[BLK];        // mask out

    const int tid   = threadIdx.x;           // 0..127
    const int batch = blockIdx.x >> 7;       // 128 blocks per batch
    const int rowBase = (blockIdx.x & 127) << 7;
    const int row   = rowBase + tid;
    const size_t ri = (size_t)batch * N + row;
    const size_t regionBase = ((size_t)batch * N + rowBase) * 7;   // floats
    const size_t gtBase     = (size_t)batch * G * 7;               // floats

    // ---- Cooperative coalesced loads: gt / rois / assign_gt block regions ----
    {
        const float4* gv = (const float4*)(gt        + gtBase);
        const float4* rv = (const float4*)(rois      + regionBase);
        const float4* av = (const float4*)(assign_gt + regionBase);
        #pragma unroll
        for (int i = tid; i < F4_PER_REGION; i += BLK) {
            ((float4*)sGT)[i] = gv[i];
            ((float4*)sRO)[i] = rv[i];
            ((float4*)sAG)[i] = av[i];
        }
    }
    __syncthreads();

    // ---- GT preamble: one box per thread, from staged sGT ----
    {
        const float* gp = sGT + tid * 7;
        float cx = gp[0], cy = gp[1], cz = gp[2];
        float dx = gp[3], dy = gp[4], dz = gp[5];
        float h  = gp[6];
        sMin[tid] = make_float4(cx - 0.5f * dx, cy - 0.5f * dy, cz - 0.5f * dz,
                                dx * dy * dz);
        sMax[tid] = make_float4(cx + 0.5f * dx, cy + 0.5f * dy, cz + 0.5f * dz, 0.f);
        sBox[tid][0] = cx; sBox[tid][1] = cy; sBox[tid][2] = cz;
        sBox[tid][3] = dx; sBox[tid][4] = dy; sBox[tid][5] = dz;
        sBox[tid][6] = -h;  // heading multiplied by -1 per reference
        sBox[tid][7] = __int_as_float(gt_lab[(size_t)batch * G + tid]);

        const int p = tid >> 1, lane = tid & 1;
        float* pc = (float*)&sCXY[p];
        pc[0 + lane] = -cx;  pc[2 + lane] = -cy;
        sCZ[tid] = -cz;

        float rb = 0.5f * sqrtf(dx * dx + dy * dy + dz * dz);
        #pragma unroll
        for (int s = 16; s; s >>= 1)
            rb = fmaxf(rb, __shfl_xor_sync(0xffffffffu, rb, s));
        if ((tid & 31) == 0) sRbMax[tid >> 5] = rb;
    }
    __syncthreads();
    const float rbmax = fmaxf(fmaxf(sRbMax[0], sRbMax[1]),
                              fmaxf(sRbMax[2], sRbMax[3]));

    // ---- My ROI from staged sRO (conflict-free stride-7 LDS) ----
    const float r0 = sRO[tid * 7 + 0], r1 = sRO[tid * 7 + 1], r2 = sRO[tid * 7 + 2];
    const float r3 = sRO[tid * 7 + 3], r4 = sRO[tid * 7 + 4], r5 = sRO[tid * 7 + 5];
    const float r6 = sRO[tid * 7 + 6];

    const float aminx = r0 - 0.5f * r3, amaxx = r0 + 0.5f * r3;
    const float aminy = r1 - 0.5f * r4, amaxy = r1 + 0.5f * r4;
    const float aminz = r2 - 0.5f * r5, amaxz = r2 + 0.5f * r5;
    const float va = r3 * r4 * r5;
    const float ra = 0.5f * sqrtf(r3 * r3 + r4 * r4 + r5 * r5);

    // Filter constant: inter>0 => dsq < (ra+rb_g)^2 <= (ra+rbmax)^2 < C
    // (Cauchy-Schwarz). +0.5 margin absorbs all fp rounding; '<=' compare
    // keeps it conservative, so the filter is exactly lossless: zero-inter
    // pairs can never win the strict-'>' argmax.
    const float Cr = ra + rbmax + 0.5f;
    const float C  = Cr * Cr;

    const ull ax2 = pk2(r0, r0);
    const ull ay2 = pk2(r1, r1);
    const ull az2 = pk2(r2, r2);

    // ---- Phase 1: packed sphere filter, 2 boxes per step; OR-tree masks ----
    unsigned mk[4];
    #pragma unroll
    for (int c = 0; c < 4; ++c) {
        unsigned t[16];
        #pragma unroll
        for (int i = 0; i < 16; ++i) {
            const int p = c * 16 + i;
            const ulonglong2 qxy = *(const ulonglong2*)&sCXY[p];
            const ull qz = *(const ull*)&sCZ[2 * p];
            const ull dx2 = add2(ax2, qxy.x);
            const ull dy2 = add2(ay2, qxy.y);
            const ull dz2 = add2(az2, qz);
            ull s2 = mul2(dx2, dx2);
            s2 = fma2(dy2, dy2, s2);
            s2 = fma2(dz2, dz2, s2);
            float s_lo, s_hi;
            upk2(s2, s_lo, s_hi);
            t[i] = (s_lo <= C ? (1u << (2 * i)) : 0u)
                 | (s_hi <= C ? (2u << (2 * i)) : 0u);
        }
        #pragma unroll
        for (int stp = 1; stp < 16; stp <<= 1)
            #pragma unroll
            for (int i = 0; i < 16; i += 2 * stp)
                t[i] |= t[i + stp];
        mk[c] = t[0];
    }

    // ---- Phase 2: exact IoU-argmax over survivors (ascending g order) ----
    // iou = inter/(s - inter), s = va + vb, strictly monotone in inter/s
    // => argmax via cross-mult compare; strict '>' keeps first max (jnp.argmax).
    float bi = 0.f, bs = 1.f; int bg = 0;
    #pragma unroll
    for (int c = 0; c < 4; ++c) {
        unsigned m = mk[c];
        while (m) {
            const int b = __ffs(m) - 1;
            m &= m - 1;
            const int g = c * 32 + b;
            const float4 mn = sMin[g];
            const float4 mx = sMax[g];
            float ox = fminf(amaxx, mx.x) - fmaxf(aminx, mn.x);
            float oy = fminf(amaxy, mx.y) - fmaxf(aminy, mn.y);
            float oz = fminf(amaxz, mx.z) - fmaxf(aminz, mn.z);
            ox = fmaxf(ox, 0.0f);
            oy = fmaxf(oy, 0.0f);
            oz = fmaxf(oz, 0.0f);
            const float inter = ox * oy * oz;
            const float s     = va + mn.w;
            if (inter * bs > bi * s) { bi = inter; bs = s; bg = g; }
        }
    }

    const int  alab = assign_lab[ri];   // coalesced 1 int/thread
    const bool pos1 = (alab >= 0);
    // max_ov >= THRESH  <=>  bi >= THRESH * clip(s - bi, 1e-6)
    const bool pos2 = (!pos1) && (bi >= THRESH * fmaxf(bs - bi, 1e-6f));

    // ---- Epilogue into staging (per-row in-place reuse is hazard-free:
    // each thread reads/writes only its own stride-7 row) ----
    #pragma unroll
    for (int k = 0; k < 7; ++k) {
        float gv;
        if (pos1) {
            gv = sAG[tid * 7 + k];
            if (k == 6) gv = -gv;   // assign_gt heading negated per reference
        } else if (pos2) {
            gv = sBox[bg][k];       // heading already negated at store time
        } else {
            gv = 0.0f;              // must write: d_out is poisoned
        }
        sGT[tid * 7 + k] = gv;      // sGT now holds gt_of_rois rows
    }
    // sRO already holds the rois rows (passthrough) - leave as is.
    int lab = pos1 ? alab : (pos2 ? __float_as_int(sBox[bg][7]) : NC);
    sL[tid] = (float)lab;
    sM[tid] = (pos1 || pos2) ? 1.0f : 0.0f;
    __syncthreads();

    // ---- Cooperative coalesced stores ----
    {
        float4* orr = (float4*)(out + regionBase);                        // rois
        float4* ogt = (float4*)(out + (size_t)B * N * 7 + regionBase);    // gt
        #pragma unroll
        for (int i = tid; i < F4_PER_REGION; i += BLK) {
            orr[i] = ((const float4*)sRO)[i];
            ogt[i] = ((const float4*)sGT)[i];
        }
        float* labBase  = out + (size_t)B * N * 14 + (size_t)batch * N + rowBase;
        float* maskBase = labBase + (size_t)B * N;
        if (tid < BLK / 4) {
            ((float4*)labBase)[tid]  = ((const float4*)sL)[tid];
            ((float4*)maskBase)[tid] = ((const float4*)sM)[tid];
        }
    }
}

extern "C" void kernel_launch(void* const* d_in, const int* in_sizes, int n_in,
                              void* d_out, int out_size)
{
    const float* rois       = (const float*)d_in[0]; // [B,N,7]
    const float* gt         = (const float*)d_in[1]; // [B,G,7]
    const int*   gt_lab     = (const int*)  d_in[2]; // [B,G]
    const float* assign_gt  = (const float*)d_in[3]; // [B,N,7]
    const int*   assign_lab = (const int*)  d_in[4]; // [B,N]
    float*       out        = (float*)d_out;

    // B*N threads, 128 per block; 128 blocks per batch
    ptl_kernel<<<(B * N) / BLK, BLK>>>(rois, gt, gt_lab, assign_gt, assign_lab, out);
}

// round 10
// speedup vs baseline: 1.2917x; 1.0025x over previous
#include <cuda_runtime.h>
#include <cuda_bf16.h>

// Problem constants (fixed by setup_inputs)
constexpr int B  = 8;
constexpr int N  = 16384;
constexpr int G  = 128;
constexpr int NC = 11;          // N_CLASSES
constexpr float THRESH = 0.3f;  // REG_FG_THRESH
constexpr int BLK = 128;
constexpr int F4_PER_REGION = BLK * 7 / 4;   // 224 float4 per 128-row x 7 region

// ---- packed f32x2 helpers (Blackwell sm_103a) ----
typedef unsigned long long ull;
__device__ __forceinline__ ull pk2(float lo, float hi) {
    ull r; asm("mov.b64 %0,{%1,%2};" : "=l"(r) : "f"(lo), "f"(hi)); return r;
}
__device__ __forceinline__ void upk2(ull v, float& lo, float& hi) {
    asm("mov.b64 {%0,%1},%2;" : "=f"(lo), "=f"(hi) : "l"(v));
}
__device__ __forceinline__ ull add2(ull a, ull b) {
    ull r; asm("add.rn.f32x2 %0,%1,%2;" : "=l"(r) : "l"(a), "l"(b)); return r;
}
__device__ __forceinline__ ull mul2(ull a, ull b) {
    ull r; asm("mul.rn.f32x2 %0,%1,%2;" : "=l"(r) : "l"(a), "l"(b)); return r;
}
__device__ __forceinline__ ull fma2(ull a, ull b, ull c) {
    ull r; asm("fma.rn.f32x2 %0,%1,%2,%3;" : "=l"(r) : "l"(a), "l"(b), "l"(c)); return r;
}

// Output layout (concatenated, float32):
//   [0,            B*N*7)   batch_rois
//   [B*N*7,        2*B*N*7) gt_of_rois
//   [2*B*N*7,      +B*N)    gt_label_of_rois (as float)
//   [2*B*N*7+B*N,  +B*N)    reg_valid_mask

__global__ __launch_bounds__(BLK)
void ptl_kernel(const float* __restrict__ rois,
                const float* __restrict__ gt,
                const int*   __restrict__ gt_lab,
                const float* __restrict__ assign_gt,
                const int*   __restrict__ assign_lab,
                float* __restrict__ out)
{
    // GT tables
    // Quad-packed filter data: quad q covers boxes 4q..4q+3.
    //   sQX[q] = (-cx0,-cx1,-cx2,-cx3)  -> 2 packed u64 per LDS.128
    //   sQY[q], sQZ[q] likewise.
    __shared__ float4 sQX[G / 4];
    __shared__ float4 sQY[G / 4];
    __shared__ float4 sQZ[G / 4];
    __shared__ float4 sMin[G];         // bmin.xyz, vol_b
    __shared__ float4 sMax[G];         // bmax.xyz, pad
    __shared__ float  sBox[G][8];      // cx cy cz dx dy dz (-h) label_bits
    __shared__ float  sRbMax[4];
    // Staging buffers (row r occupies [r*7, r*7+7); stride 7 coprime to 32
    // -> conflict-free scalar LDS/STS per row)
    __shared__ alignas(16) float sGT[BLK * 7];   // gt in -> gt_of_rois out
    __shared__ alignas(16) float sRO[BLK * 7];   // rois in -> rois passthrough out
    __shared__ alignas(16) float sAG[BLK * 7];   // assign_gt in
    __shared__ alignas(16) float sL[BLK];        // label out
    __shared__ alignas(16) float sM[BLK];        // mask out

    const int tid   = threadIdx.x;           // 0..127
    const int batch = blockIdx.x >> 7;       // 128 blocks per batch
    const int rowBase = (blockIdx.x & 127) << 7;
    const int row   = rowBase + tid;
    const size_t ri = (size_t)batch * N + row;
    const size_t regionBase = ((size_t)batch * N + rowBase) * 7;   // floats
    const size_t gtBase     = (size_t)batch * G * 7;               // floats

    // ---- Cooperative coalesced loads: gt / rois / assign_gt block regions ----
    {
        const float4* gv = (const float4*)(gt        + gtBase);
        const float4* rv = (const float4*)(rois      + regionBase);
        const float4* av = (const float4*)(assign_gt + regionBase);
        #pragma unroll
        for (int i = tid; i < F4_PER_REGION; i += BLK) {
            ((float4*)sGT)[i] = gv[i];
            ((float4*)sRO)[i] = rv[i];
            ((float4*)sAG)[i] = av[i];
        }
    }
    __syncthreads();

    // ---- GT preamble: one box per thread, from staged sGT ----
    {
        const float* gp = sGT + tid * 7;
        float cx = gp[0], cy = gp[1], cz = gp[2];
        float dx = gp[3], dy = gp[4], dz = gp[5];
        float h  = gp[6];
        sMin[tid] = make_float4(cx - 0.5f * dx, cy - 0.5f * dy, cz - 0.5f * dz,
                                dx * dy * dz);
        sMax[tid] = make_float4(cx + 0.5f * dx, cy + 0.5f * dy, cz + 0.5f * dz, 0.f);
        sBox[tid][0] = cx; sBox[tid][1] = cy; sBox[tid][2] = cz;
        sBox[tid][3] = dx; sBox[tid][4] = dy; sBox[tid][5] = dz;
        sBox[tid][6] = -h;  // heading multiplied by -1 per reference
        sBox[tid][7] = __int_as_float(gt_lab[(size_t)batch * G + tid]);

        const int q = tid >> 2, r = tid & 3;
        ((float*)&sQX[q])[r] = -cx;
        ((float*)&sQY[q])[r] = -cy;
        ((float*)&sQZ[q])[r] = -cz;

        float rb = 0.5f * sqrtf(dx * dx + dy * dy + dz * dz);
        #pragma unroll
        for (int s = 16; s; s >>= 1)
            rb = fmaxf(rb, __shfl_xor_sync(0xffffffffu, rb, s));
        if ((tid & 31) == 0) sRbMax[tid >> 5] = rb;
    }
    __syncthreads();
    const float rbmax = fmaxf(fmaxf(sRbMax[0], sRbMax[1]),
                              fmaxf(sRbMax[2], sRbMax[3]));

    // ---- My ROI from staged sRO (conflict-free stride-7 LDS) ----
    const float r0 = sRO[tid * 7 + 0], r1 = sRO[tid * 7 + 1], r2 = sRO[tid * 7 + 2];
    const float r3 = sRO[tid * 7 + 3], r4 = sRO[tid * 7 + 4], r5 = sRO[tid * 7 + 5];
    const float r6 = sRO[tid * 7 + 6];

    const float aminx = r0 - 0.5f * r3, amaxx = r0 + 0.5f * r3;
    const float aminy = r1 - 0.5f * r4, amaxy = r1 + 0.5f * r4;
    const float aminz = r2 - 0.5f * r5, amaxz = r2 + 0.5f * r5;
    const float va = r3 * r4 * r5;
    const float ra = 0.5f * sqrtf(r3 * r3 + r4 * r4 + r5 * r5);

    // Filter constant: inter>0 => dsq < (ra+rb_g)^2 <= (ra+rbmax)^2 < C
    // (Cauchy-Schwarz). +0.5 margin absorbs all fp rounding; '<=' compare
    // keeps it conservative, so the filter is exactly lossless: zero-inter
    // pairs can never win the strict-'>' argmax.
    const float Cr = ra + rbmax + 0.5f;
    const float C  = Cr * Cr;

    const ull ax2 = pk2(r0, r0);
    const ull ay2 = pk2(r1, r1);
    const ull az2 = pk2(r2, r2);

    // ---- Phase 1: quad-packed sphere filter, 4 boxes per step ----
    // 3 LDS.128 serve 4 boxes; masks built by OR tree (independent dataflow).
    unsigned mk[4];
    #pragma unroll
    for (int c = 0; c < 4; ++c) {
        unsigned t[8];
        #pragma unroll
        for (int i = 0; i < 8; ++i) {
            const int q = c * 8 + i;
            const ulonglong2 qx = *(const ulonglong2*)&sQX[q];
            const ulonglong2 qy = *(const ulonglong2*)&sQY[q];
            const ulonglong2 qz = *(const ulonglong2*)&sQZ[q];
            // boxes 4q, 4q+1
            const ull dxA = add2(ax2, qx.x);
            const ull dyA = add2(ay2, qy.x);
            const ull dzA = add2(az2, qz.x);
            ull sA = mul2(dxA, dxA);
            sA = fma2(dyA, dyA, sA);
            sA = fma2(dzA, dzA, sA);
            // boxes 4q+2, 4q+3
            const ull dxB = add2(ax2, qx.y);
            const ull dyB = add2(ay2, qy.y);
            const ull dzB = add2(az2, qz.y);
            ull sB = mul2(dxB, dxB);
            sB = fma2(dyB, dyB, sB);
            sB = fma2(dzB, dzB, sB);
            float a0, a1, b0, b1;
            upk2(sA, a0, a1);
            upk2(sB, b0, b1);
            t[i] = (a0 <= C ? (1u << (4 * i))     : 0u)
                 | (a1 <= C ? (2u << (4 * i))     : 0u)
                 | (b0 <= C ? (4u << (4 * i))     : 0u)
                 | (b1 <= C ? (8u << (4 * i))     : 0u);
        }
        // binary OR tree, depth 3
        #pragma unroll
        for (int stp = 1; stp < 8; stp <<= 1)
            #pragma unroll
            for (int i = 0; i < 8; i += 2 * stp)
                t[i] |= t[i + stp];
        mk[c] = t[0];
    }

    // ---- Phase 2: exact IoU-argmax over survivors (ascending g order) ----
    // iou = inter/(s - inter), s = va + vb, strictly monotone in inter/s
    // => argmax via cross-mult compare; strict '>' keeps first max (jnp.argmax).
    float bi = 0.f, bs = 1.f; int bg = 0;
    #pragma unroll
    for (int c = 0; c < 4; ++c) {
        unsigned m = mk[c];
        while (m) {
            const int b = __ffs(m) - 1;
            m &= m - 1;
            const int g = c * 32 + b;
            const float4 mn = sMin[g];
            const float4 mx = sMax[g];
            float ox = fminf(amaxx, mx.x) - fmaxf(aminx, mn.x);
            float oy = fminf(amaxy, mx.y) - fmaxf(aminy, mn.y);
            float oz = fminf(amaxz, mx.z) - fmaxf(aminz, mn.z);
            ox = fmaxf(ox, 0.0f);
            oy = fmaxf(oy, 0.0f);
            oz = fmaxf(oz, 0.0f);
            const float inter = ox * oy * oz;
            const float s     = va + mn.w;
            if (inter * bs > bi * s) { bi = inter; bs = s; bg = g; }
        }
    }

    const int  alab = assign_lab[ri];   // coalesced 1 int/thread
    const bool pos1 = (alab >= 0);
    // max_ov >= THRESH  <=>  bi >= THRESH * clip(s - bi, 1e-6)
    const bool pos2 = (!pos1) && (bi >= THRESH * fmaxf(bs - bi, 1e-6f));

    // ---- Epilogue into staging (per-row in-place reuse is hazard-free:
    // each thread reads/writes only its own stride-7 row) ----
    #pragma unroll
    for (int k = 0; k < 7; ++k) {
        float gv;
        if (pos1) {
            gv = sAG[tid * 7 + k];
            if (k == 6) gv = -gv;   // assign_gt heading negated per reference
        } else if (pos2) {
            gv = sBox[bg][k];       // heading already negated at store time
        } else {
            gv = 0.0f;              // must write: d_out is poisoned
        }
        sGT[tid * 7 + k] = gv;      // sGT now holds gt_of_rois rows
    }
    // sRO already holds the rois rows (passthrough) - leave as is.
    int lab = pos1 ? alab : (pos2 ? __float_as_int(sBox[bg][7]) : NC);
    sL[tid] = (float)lab;
    sM[tid] = (pos1 || pos2) ? 1.0f : 0.0f;
    __syncthreads();

    // ---- Cooperative coalesced stores ----
    {
        float4* orr = (float4*)(out + regionBase);                        // rois
        float4* ogt = (float4*)(out + (size_t)B * N * 7 + regionBase);    // gt
        #pragma unroll
        for (int i = tid; i < F4_PER_REGION; i += BLK) {
            orr[i] = ((const float4*)sRO)[i];
            ogt[i] = ((const float4*)sGT)[i];
        }
        float* labBase  = out + (size_t)B * N * 14 + (size_t)batch * N + rowBase;
        float* maskBase = labBase + (size_t)B * N;
        if (tid < BLK / 4) {
            ((float4*)labBase)[tid]  = ((const float4*)sL)[tid];
            ((float4*)maskBase)[tid] = ((const float4*)sM)[tid];
        }
    }
}

extern "C" void kernel_launch(void* const* d_in, const int* in_sizes, int n_in,
                              void* d_out, int out_size)
{
    const float* rois       = (const float*)d_in[0]; // [B,N,7]
    const float* gt         = (const float*)d_in[1]; // [B,G,7]
    const int*   gt_lab     = (const int*)  d_in[2]; // [B,G]
    const float* assign_gt  = (const float*)d_in[3]; // [B,N,7]
    const int*   assign_lab = (const int*)  d_in[4]; // [B,N]
    float*       out        = (float*)d_out;

    // B*N threads, 128 per block; 128 blocks per batch
    ptl_kernel<<<(B * N) / BLK, BLK>>>(rois, gt, gt_lab, assign_gt, assign_lab, out);
}

// round 11
// speedup vs baseline: 1.5364x; 1.1895x over previous
#include <cuda_runtime.h>
#include <cuda_bf16.h>

// Problem constants (fixed by setup_inputs)
constexpr int B  = 8;
constexpr int N  = 16384;
constexpr int G  = 128;
constexpr int NC = 11;          // N_CLASSES
constexpr float THRESH = 0.3f;  // REG_FG_THRESH
constexpr int BLK = 128;
constexpr int F4_PER_REGION = BLK * 7 / 4;   // 224 float4 per 128-row x 7 region

constexpr int   NBUCK   = 16;
constexpr float BUCK_LO  = -50.0f;
constexpr float BUCK_INV = 0.16f;     // 1 / 6.25
constexpr float MARGIN   = 0.125f;

__device__ __forceinline__ int bidx(float v) {
    int k = (int)floorf((v - BUCK_LO) * BUCK_INV);
    return min(max(k, 0), NBUCK - 1);
}

// Output layout (concatenated, float32):
//   [0,            B*N*7)   batch_rois
//   [B*N*7,        2*B*N*7) gt_of_rois
//   [2*B*N*7,      +B*N)    gt_label_of_rois (as float)
//   [2*B*N*7+B*N,  +B*N)    reg_valid_mask

__global__ __launch_bounds__(BLK)
void ptl_kernel(const float* __restrict__ rois,
                const float* __restrict__ gt,
                const int*   __restrict__ gt_lab,
                const float* __restrict__ assign_gt,
                const int*   __restrict__ assign_lab,
                float* __restrict__ out)
{
    // GT tables
    __shared__ float4 sMin[G];         // bmin.xyz, vol_b
    __shared__ float4 sMax[G];         // bmax.xyz, pad
    __shared__ float  sBox[G][8];      // cx cy cz dx dy dz (-h) label_bits
    // Per-axis bucket masks: sMsk[a][k] = 128-bit mask (uint4) of boxes whose
    // axis-a interval (with margin) intersects bucket k.
    __shared__ uint4  sMsk[3][NBUCK];
    // Staging buffers (row r occupies [r*7, r*7+7); stride 7 coprime to 32
    // -> conflict-free scalar LDS/STS per row)
    __shared__ alignas(16) float sGT[BLK * 7];   // gt in -> gt_of_rois out
    __shared__ alignas(16) float sRO[BLK * 7];   // rois in -> rois passthrough out
    __shared__ alignas(16) float sAG[BLK * 7];   // assign_gt in
    __shared__ alignas(16) float sL[BLK];        // label out
    __shared__ alignas(16) float sM[BLK];        // mask out

    const int tid   = threadIdx.x;           // 0..127
    const int batch = blockIdx.x >> 7;       // 128 blocks per batch
    const int rowBase = (blockIdx.x & 127) << 7;
    const size_t ri = (size_t)batch * N + rowBase + tid;
    const size_t regionBase = ((size_t)batch * N + rowBase) * 7;   // floats
    const size_t gtBase     = (size_t)batch * G * 7;               // floats

    // ---- Zero bucket masks + cooperative coalesced loads ----
    {
        unsigned* mw = (unsigned*)sMsk;          // 3*16*4 = 192 words
        #pragma unroll
        for (int i = tid; i < 192; i += BLK) mw[i] = 0u;

        const float4* gv = (const float4*)(gt        + gtBase);
        const float4* rv = (const float4*)(rois      + regionBase);
        const float4* av = (const float4*)(assign_gt + regionBase);
        #pragma unroll
        for (int i = tid; i < F4_PER_REGION; i += BLK) {
            ((float4*)sGT)[i] = gv[i];
            ((float4*)sRO)[i] = rv[i];
            ((float4*)sAG)[i] = av[i];
        }
    }
    __syncthreads();

    // ---- GT preamble: one box per thread; build tables + bucket masks ----
    {
        const float* gp = sGT + tid * 7;
        float cx = gp[0], cy = gp[1], cz = gp[2];
        float dx = gp[3], dy = gp[4], dz = gp[5];
        float h  = gp[6];
        float bmn[3] = { cx - 0.5f * dx, cy - 0.5f * dy, cz - 0.5f * dz };
        float bmx[3] = { cx + 0.5f * dx, cy + 0.5f * dy, cz + 0.5f * dz };
        sMin[tid] = make_float4(bmn[0], bmn[1], bmn[2], dx * dy * dz);
        sMax[tid] = make_float4(bmx[0], bmx[1], bmx[2], 0.f);
        sBox[tid][0] = cx; sBox[tid][1] = cy; sBox[tid][2] = cz;
        sBox[tid][3] = dx; sBox[tid][4] = dy; sBox[tid][5] = dz;
        sBox[tid][6] = -h;  // heading multiplied by -1 per reference
        sBox[tid][7] = __int_as_float(gt_lab[(size_t)batch * G + tid]);

        const unsigned bit = 1u << (tid & 31);
        const int w = tid >> 5;
        #pragma unroll
        for (int a = 0; a < 3; ++a) {
            const int ka = bidx(bmn[a] - MARGIN);
            const int kb = bidx(bmx[a] + MARGIN);
            for (int k = ka; k <= kb; ++k)
                atomicOr(((unsigned*)&sMsk[a][k]) + w, bit);
        }
    }
    __syncthreads();

    // ---- My ROI from staged sRO (conflict-free stride-7 LDS) ----
    const float r0 = sRO[tid * 7 + 0], r1 = sRO[tid * 7 + 1], r2 = sRO[tid * 7 + 2];
    const float r3 = sRO[tid * 7 + 3], r4 = sRO[tid * 7 + 4], r5 = sRO[tid * 7 + 5];
    const float r6 = sRO[tid * 7 + 6];

    const float aminx = r0 - 0.5f * r3, amaxx = r0 + 0.5f * r3;
    const float aminy = r1 - 0.5f * r4, amaxy = r1 + 0.5f * r4;
    const float aminz = r2 - 0.5f * r5, amaxz = r2 + 0.5f * r5;
    const float va = r3 * r4 * r5;

    // ---- Candidate mask: OR bucket masks per axis over ROI's bucket span,
    // then AND across axes. A box overlapping the ROI on axis a has its
    // interval intersecting the ROI interval, which lies within buckets
    // k0..k1 -> box present in the ORed mask. Margins dwarf fp rounding,
    // so the mask is conservative; zero-inter boxes can never win the
    // strict-'>' argmax, making the filter exactly lossless.
    unsigned cand[4];
    {
        const float lo[3] = { aminx - MARGIN, aminy - MARGIN, aminz - MARGIN };
        const float hi[3] = { amaxx + MARGIN, amaxy + MARGIN, amaxz + MARGIN };
        #pragma unroll
        for (int a = 0; a < 3; ++a) {
            const int k0 = bidx(lo[a]);
            const int k1 = bidx(hi[a]);
            uint4 m = sMsk[a][k0];
            for (int k = k0 + 1; k <= k1; ++k) {
                const uint4 mm = sMsk[a][k];
                m.x |= mm.x; m.y |= mm.y; m.z |= mm.z; m.w |= mm.w;
            }
            if (a == 0) { cand[0] = m.x; cand[1] = m.y; cand[2] = m.z; cand[3] = m.w; }
            else        { cand[0] &= m.x; cand[1] &= m.y; cand[2] &= m.z; cand[3] &= m.w; }
        }
    }

    // ---- Exact IoU-argmax over candidates (ascending g order) ----
    // iou = inter/(s - inter), s = va + vb, strictly monotone in inter/s
    // => argmax via cross-mult compare; strict '>' keeps first max (jnp.argmax).
    float bi = 0.f, bs = 1.f; int bg = 0;
    #pragma unroll
    for (int c = 0; c < 4; ++c) {
        unsigned m = cand[c];
        while (m) {
            const int b = __ffs(m) - 1;
            m &= m - 1;
            const int g = c * 32 + b;
            const float4 mn = sMin[g];
            const float4 mx = sMax[g];
            float ox = fminf(amaxx, mx.x) - fmaxf(aminx, mn.x);
            float oy = fminf(amaxy, mx.y) - fmaxf(aminy, mn.y);
            float oz = fminf(amaxz, mx.z) - fmaxf(aminz, mn.z);
            ox = fmaxf(ox, 0.0f);
            oy = fmaxf(oy, 0.0f);
            oz = fmaxf(oz, 0.0f);
            const float inter = ox * oy * oz;
            const float s     = va + mn.w;
            if (inter * bs > bi * s) { bi = inter; bs = s; bg = g; }
        }
    }

    const int  alab = assign_lab[ri];   // coalesced 1 int/thread
    const bool pos1 = (alab >= 0);
    // max_ov >= THRESH  <=>  bi >= THRESH * clip(s - bi, 1e-6)
    const bool pos2 = (!pos1) && (bi >= THRESH * fmaxf(bs - bi, 1e-6f));

    // ---- Epilogue into staging (per-row in-place reuse is hazard-free:
    // each thread reads/writes only its own stride-7 row) ----
    #pragma unroll
    for (int k = 0; k < 7; ++k) {
        float gv;
        if (pos1) {
            gv = sAG[tid * 7 + k];
            if (k == 6) gv = -gv;   // assign_gt heading negated per reference
        } else if (pos2) {
            gv = sBox[bg][k];       // heading already negated at store time
        } else {
            gv = 0.0f;              // must write: d_out is poisoned
        }
        sGT[tid * 7 + k] = gv;      // sGT now holds gt_of_rois rows
    }
    // sRO already holds the rois rows (passthrough) - leave as is.
    int lab = pos1 ? alab : (pos2 ? __float_as_int(sBox[bg][7]) : NC);
    sL[tid] = (float)lab;
    sM[tid] = (pos1 || pos2) ? 1.0f : 0.0f;
    __syncthreads();

    // ---- Cooperative coalesced stores ----
    {
        float4* orr = (float4*)(out + regionBase);                        // rois
        float4* ogt = (float4*)(out + (size_t)B * N * 7 + regionBase);    // gt
        #pragma unroll
        for (int i = tid; i < F4_PER_REGION; i += BLK) {
            orr[i] = ((const float4*)sRO)[i];
            ogt[i] = ((const float4*)sGT)[i];
        }
        float* labBase  = out + (size_t)B * N * 14 + (size_t)batch * N + rowBase;
        float* maskBase = labBase + (size_t)B * N;
        if (tid < BLK / 4) {
            ((float4*)labBase)[tid]  = ((const float4*)sL)[tid];
            ((float4*)maskBase)[tid] = ((const float4*)sM)[tid];
        }
    }
}

extern "C" void kernel_launch(void* const* d_in, const int* in_sizes, int n_in,
                              void* d_out, int out_size)
{
    const float* rois       = (const float*)d_in[0]; // [B,N,7]
    const float* gt         = (const float*)d_in[1]; // [B,G,7]
    const int*   gt_lab     = (const int*)  d_in[2]; // [B,G]
    const float* assign_gt  = (const float*)d_in[3]; // [B,N,7]
    const int*   assign_lab = (const int*)  d_in[4]; // [B,N]
    float*       out        = (float*)d_out;

    // B*N threads, 128 per block; 128 blocks per batch
    ptl_kernel<<<(B * N) / BLK, BLK>>>(rois, gt, gt_lab, assign_gt, assign_lab, out);
}

// round 12
// speedup vs baseline: 1.5731x; 1.0239x over previous
#include <cuda_runtime.h>
#include <cuda_bf16.h>

// Problem constants (fixed by setup_inputs)
constexpr int B  = 8;
constexpr int N  = 16384;
constexpr int G  = 128;
constexpr int NC = 11;          // N_CLASSES
constexpr float THRESH = 0.3f;  // REG_FG_THRESH
constexpr int BLK  = 256;                       // threads per block == rows per block
constexpr int BLOCKS_PER_BATCH = N / BLK;       // 64
constexpr int F4_ROWS = BLK * 7 / 4;            // 448 float4 per row-region
constexpr int F4_GT   = G * 7 / 4;              // 224 float4 for the gt region

constexpr int   NBUCK   = 16;
constexpr float BUCK_LO  = -50.0f;
constexpr float BUCK_INV = 0.16f;     // 1 / 6.25
constexpr float MARGIN   = 0.125f;

__device__ __forceinline__ int bidx(float v) {
    int k = (int)floorf((v - BUCK_LO) * BUCK_INV);
    return min(max(k, 0), NBUCK - 1);
}

// ---- cp.async helpers ----
__device__ __forceinline__ void cpa16(void* smem, const void* gmem) {
    unsigned saddr = (unsigned)__cvta_generic_to_shared(smem);
    asm volatile("cp.async.ca.shared.global [%0], [%1], 16;"
                 :: "r"(saddr), "l"(gmem));
}
__device__ __forceinline__ void cpa_commit() {
    asm volatile("cp.async.commit_group;");
}
template <int NLeft>
__device__ __forceinline__ void cpa_wait() {
    asm volatile("cp.async.wait_group %0;" :: "n"(NLeft));
}

// Output layout (concatenated, float32):
//   [0,            B*N*7)   batch_rois
//   [B*N*7,        2*B*N*7) gt_of_rois
//   [2*B*N*7,      +B*N)    gt_label_of_rois (as float)
//   [2*B*N*7+B*N,  +B*N)    reg_valid_mask

__global__ __launch_bounds__(BLK)
void ptl_kernel(const float* __restrict__ rois,
                const float* __restrict__ gt,
                const int*   __restrict__ gt_lab,
                const float* __restrict__ assign_gt,
                const int*   __restrict__ assign_lab,
                float* __restrict__ out)
{
    // GT tables
    __shared__ float4 sMin[G];         // bmin.xyz, vol_b
    __shared__ float4 sMax[G];         // bmax.xyz, pad
    __shared__ float  sBox[G][8];      // cx cy cz dx dy dz (-h) label_bits
    // Per-axis bucket masks: sMsk[a][k] = 128-bit mask (uint4) of boxes whose
    // axis-a interval (with margin) intersects bucket k.
    __shared__ uint4  sMsk[3][NBUCK];
    // Staging buffers (row r occupies [r*7, r*7+7); stride 7 coprime to 32
    // -> conflict-free scalar LDS/STS per row)
    __shared__ alignas(16) float sGTin[G * 7];   // gt input (896 floats)
    __shared__ alignas(16) float sGO[BLK * 7];   // gt_of_rois out
    __shared__ alignas(16) float sRO[BLK * 7];   // rois in -> passthrough out
    __shared__ alignas(16) float sAG[BLK * 7];   // assign_gt in
    __shared__ alignas(16) float sL[BLK];        // label out
    __shared__ alignas(16) float sM[BLK];        // mask out

    const int tid   = threadIdx.x;                  // 0..255
    const int batch = blockIdx.x / BLOCKS_PER_BATCH;
    const int rowBase = (blockIdx.x % BLOCKS_PER_BATCH) * BLK;
    const size_t ri = (size_t)batch * N + rowBase + tid;
    const size_t regionBase = ((size_t)batch * N + rowBase) * 7;   // floats
    const size_t gtBase     = (size_t)batch * G * 7;               // floats

    // ---- Async staging: group A = gt region, group B = rois + assign_gt ----
    {
        // group A: 224 float4, threads 0..223
        if (tid < F4_GT)
            cpa16(((float4*)sGTin) + tid, ((const float4*)(gt + gtBase)) + tid);
        cpa_commit();
        // group B: rois + assign_gt, 448 float4 each
        #pragma unroll
        for (int i = tid; i < F4_ROWS; i += BLK) {
            cpa16(((float4*)sRO) + i, ((const float4*)(rois      + regionBase)) + i);
            cpa16(((float4*)sAG) + i, ((const float4*)(assign_gt + regionBase)) + i);
        }
        cpa_commit();

        // zero bucket masks while copies are in flight
        unsigned* mw = (unsigned*)sMsk;          // 3*16*4 = 192 words
        if (tid < 192) mw[tid] = 0u;
    }
    cpa_wait<1>();       // gt region resident (rois/assign_gt may still fly)
    __syncthreads();

    // ---- GT preamble: one box per thread (tid < G) ----
    if (tid < G) {
        const float* gp = sGTin + tid * 7;
        float cx = gp[0], cy = gp[1], cz = gp[2];
        float dx = gp[3], dy = gp[4], dz = gp[5];
        float h  = gp[6];
        float bmn[3] = { cx - 0.5f * dx, cy - 0.5f * dy, cz - 0.5f * dz };
        float bmx[3] = { cx + 0.5f * dx, cy + 0.5f * dy, cz + 0.5f * dz };
        sMin[tid] = make_float4(bmn[0], bmn[1], bmn[2], dx * dy * dz);
        sMax[tid] = make_float4(bmx[0], bmx[1], bmx[2], 0.f);
        sBox[tid][0] = cx; sBox[tid][1] = cy; sBox[tid][2] = cz;
        sBox[tid][3] = dx; sBox[tid][4] = dy; sBox[tid][5] = dz;
        sBox[tid][6] = -h;  // heading multiplied by -1 per reference
        sBox[tid][7] = __int_as_float(gt_lab[(size_t)batch * G + tid]);

        const unsigned bit = 1u << (tid & 31);
        const int w = tid >> 5;
        #pragma unroll
        for (int a = 0; a < 3; ++a) {
            const int ka = bidx(bmn[a] - MARGIN);
            const int kb = bidx(bmx[a] + MARGIN);
            for (int k = ka; k <= kb; ++k)
                atomicOr(((unsigned*)&sMsk[a][k]) + w, bit);
        }
    }
    cpa_wait<0>();       // rois/assign_gt resident
    __syncthreads();

    // ---- My ROI from staged sRO (conflict-free stride-7 LDS) ----
    const float r0 = sRO[tid * 7 + 0], r1 = sRO[tid * 7 + 1], r2 = sRO[tid * 7 + 2];
    const float r3 = sRO[tid * 7 + 3], r4 = sRO[tid * 7 + 4], r5 = sRO[tid * 7 + 5];

    const float aminx = r0 - 0.5f * r3, amaxx = r0 + 0.5f * r3;
    const float aminy = r1 - 0.5f * r4, amaxy = r1 + 0.5f * r4;
    const float aminz = r2 - 0.5f * r5, amaxz = r2 + 0.5f * r5;
    const float va = r3 * r4 * r5;

    // ---- Candidate mask: OR bucket masks per axis over ROI's bucket span,
    // then AND across axes. A box overlapping the ROI on axis a has its
    // interval intersecting the ROI interval, which lies within buckets
    // k0..k1 -> box present in the ORed mask. Margins dwarf fp rounding,
    // so the mask is conservative; zero-inter boxes can never win the
    // strict-'>' argmax, making the filter exactly lossless.
    unsigned cand[4];
    {
        const float lo[3] = { aminx - MARGIN, aminy - MARGIN, aminz - MARGIN };
        const float hi[3] = { amaxx + MARGIN, amaxy + MARGIN, amaxz + MARGIN };
        #pragma unroll
        for (int a = 0; a < 3; ++a) {
            const int k0 = bidx(lo[a]);
            const int k1 = bidx(hi[a]);
            uint4 m = sMsk[a][k0];
            for (int k = k0 + 1; k <= k1; ++k) {
                const uint4 mm = sMsk[a][k];
                m.x |= mm.x; m.y |= mm.y; m.z |= mm.z; m.w |= mm.w;
            }
            if (a == 0) { cand[0] = m.x; cand[1] = m.y; cand[2] = m.z; cand[3] = m.w; }
            else        { cand[0] &= m.x; cand[1] &= m.y; cand[2] &= m.z; cand[3] &= m.w; }
        }
    }

    // ---- Exact IoU-argmax over candidates (ascending g order) ----
    // iou = inter/(s - inter), s = va + vb, strictly monotone in inter/s
    // => argmax via cross-mult compare; strict '>' keeps first max (jnp.argmax).
    float bi = 0.f, bs = 1.f; int bg = 0;
    #pragma unroll
    for (int c = 0; c < 4; ++c) {
        unsigned m = cand[c];
        while (m) {
            const int b = __ffs(m) - 1;
            m &= m - 1;
            const int g = c * 32 + b;
            const float4 mn = sMin[g];
            const float4 mx = sMax[g];
            float ox = fminf(amaxx, mx.x) - fmaxf(aminx, mn.x);
            float oy = fminf(amaxy, mx.y) - fmaxf(aminy, mn.y);
            float oz = fminf(amaxz, mx.z) - fmaxf(aminz, mn.z);
            ox = fmaxf(ox, 0.0f);
            oy = fmaxf(oy, 0.0f);
            oz = fmaxf(oz, 0.0f);
            const float inter = ox * oy * oz;
            const float s     = va + mn.w;
            if (inter * bs > bi * s) { bi = inter; bs = s; bg = g; }
        }
    }

    const int  alab = assign_lab[ri];   // coalesced 1 int/thread
    const bool pos1 = (alab >= 0);
    // max_ov >= THRESH  <=>  bi >= THRESH * clip(s - bi, 1e-6)
    const bool pos2 = (!pos1) && (bi >= THRESH * fmaxf(bs - bi, 1e-6f));

    // ---- Epilogue into staging (each thread writes only its own row) ----
    #pragma unroll
    for (int k = 0; k < 7; ++k) {
        float gv;
        if (pos1) {
            gv = sAG[tid * 7 + k];
            if (k == 6) gv = -gv;   // assign_gt heading negated per reference
        } else if (pos2) {
            gv = sBox[bg][k];       // heading already negated at store time
        } else {
            gv = 0.0f;              // must write: d_out is poisoned
        }
        sGO[tid * 7 + k] = gv;
    }
    // sRO already holds the rois rows (passthrough) - leave as is.
    int lab = pos1 ? alab : (pos2 ? __float_as_int(sBox[bg][7]) : NC);
    sL[tid] = (float)lab;
    sM[tid] = (pos1 || pos2) ? 1.0f : 0.0f;
    __syncthreads();

    // ---- Cooperative coalesced stores ----
    {
        float4* orr = (float4*)(out + regionBase);                        // rois
        float4* ogt = (float4*)(out + (size_t)B * N * 7 + regionBase);    // gt
        #pragma unroll
        for (int i = tid; i < F4_ROWS; i += BLK) {
            orr[i] = ((const float4*)sRO)[i];
            ogt[i] = ((const float4*)sGO)[i];
        }
        float* labBase  = out + (size_t)B * N * 14 + (size_t)batch * N + rowBase;
        float* maskBase = labBase + (size_t)B * N;
        if (tid < BLK / 4) {
            ((float4*)labBase)[tid]  = ((const float4*)sL)[tid];
            ((float4*)maskBase)[tid] = ((const float4*)sM)[tid];
        }
    }
}

extern "C" void kernel_launch(void* const* d_in, const int* in_sizes, int n_in,
                              void* d_out, int out_size)
{
    const float* rois       = (const float*)d_in[0]; // [B,N,7]
    const float* gt         = (const float*)d_in[1]; // [B,G,7]
    const int*   gt_lab     = (const int*)  d_in[2]; // [B,G]
    const float* assign_gt  = (const float*)d_in[3]; // [B,N,7]
    const int*   assign_lab = (const int*)  d_in[4]; // [B,N]
    float*       out        = (float*)d_out;

    // 256 threads/block, 1 ROI/thread -> 512 blocks
    ptl_kernel<<<(B * N) / BLK, BLK>>>(rois, gt, gt_lab, assign_gt, assign_lab, out);
}

// round 13
// speedup vs baseline: 1.9446x; 1.2362x over previous
#include <cuda_runtime.h>
#include <cuda_bf16.h>

// Problem constants (fixed by setup_inputs)
constexpr int B  = 8;
constexpr int N  = 16384;
constexpr int G  = 128;
constexpr int NC = 11;          // N_CLASSES
constexpr float THRESH = 0.3f;  // REG_FG_THRESH
constexpr int BLK  = 128;                       // threads per block == rows per block
constexpr int BLOCKS_PER_BATCH = N / BLK;       // 128
constexpr int F4_ROWS = BLK * 7 / 4;            // 224 float4 per row-region
constexpr int F4_GT   = G * 7 / 4;              // 224 float4 for the gt region

constexpr int   NBUCK   = 16;
constexpr float BUCK_LO  = -50.0f;
constexpr float BUCK_INV = 0.16f;     // 1 / 6.25
constexpr float MARGIN   = 0.125f;

__device__ __forceinline__ int bidx(float v) {
    int k = (int)floorf((v - BUCK_LO) * BUCK_INV);
    return min(max(k, 0), NBUCK - 1);
}

// ---- cp.async helpers ----
__device__ __forceinline__ void cpa16(void* smem, const void* gmem) {
    unsigned saddr = (unsigned)__cvta_generic_to_shared(smem);
    asm volatile("cp.async.ca.shared.global [%0], [%1], 16;"
                 :: "r"(saddr), "l"(gmem));
}
__device__ __forceinline__ void cpa_commit() {
    asm volatile("cp.async.commit_group;");
}
template <int NLeft>
__device__ __forceinline__ void cpa_wait() {
    asm volatile("cp.async.wait_group %0;" :: "n"(NLeft));
}

// Output layout (concatenated, float32):
//   [0,            B*N*7)   batch_rois
//   [B*N*7,        2*B*N*7) gt_of_rois
//   [2*B*N*7,      +B*N)    gt_label_of_rois (as float)
//   [2*B*N*7+B*N,  +B*N)    reg_valid_mask

__global__ __launch_bounds__(BLK)
void ptl_kernel(const float* __restrict__ rois,
                const float* __restrict__ gt,
                const int*   __restrict__ gt_lab,
                const float* __restrict__ assign_gt,
                const int*   __restrict__ assign_lab,
                float* __restrict__ out)
{
    // GT tables
    __shared__ float4 sMin[G];         // bmin.xyz, vol_b
    __shared__ float4 sMax[G];         // bmax.xyz, pad
    __shared__ float  sBox[G][8];      // cx cy cz dx dy dz (-h) label_bits
    // Per-axis bucket masks: sMsk[a][k] = 128-bit mask (uint4) of boxes whose
    // axis-a interval (with margin) intersects bucket k.
    __shared__ uint4  sMsk[3][NBUCK];
    // Staging buffers (row r occupies [r*7, r*7+7); stride 7 coprime to 32
    // -> conflict-free scalar LDS/STS per row)
    __shared__ alignas(16) float sGTin[G * 7];   // gt input (896 floats)
    __shared__ alignas(16) float sGO[BLK * 7];   // gt_of_rois out
    __shared__ alignas(16) float sRO[BLK * 7];   // rois in -> passthrough out
    __shared__ alignas(16) float sAG[BLK * 7];   // assign_gt in

    const int tid   = threadIdx.x;                  // 0..127
    const int batch = blockIdx.x / BLOCKS_PER_BATCH;
    const int rowBase = (blockIdx.x % BLOCKS_PER_BATCH) * BLK;
    const size_t ri = (size_t)batch * N + rowBase + tid;
    const size_t regionBase = ((size_t)batch * N + rowBase) * 7;   // floats
    const size_t gtBase     = (size_t)batch * G * 7;               // floats

    // ---- Async staging: group A = gt region, group B = rois + assign_gt ----
    {
        #pragma unroll
        for (int i = tid; i < F4_GT; i += BLK)
            cpa16(((float4*)sGTin) + i, ((const float4*)(gt + gtBase)) + i);
        cpa_commit();
        #pragma unroll
        for (int i = tid; i < F4_ROWS; i += BLK) {
            cpa16(((float4*)sRO) + i, ((const float4*)(rois      + regionBase)) + i);
            cpa16(((float4*)sAG) + i, ((const float4*)(assign_gt + regionBase)) + i);
        }
        cpa_commit();

        // zero bucket masks while copies are in flight
        unsigned* mw = (unsigned*)sMsk;          // 3*16*4 = 192 words
        #pragma unroll
        for (int i = tid; i < 192; i += BLK) mw[i] = 0u;
    }
    cpa_wait<1>();       // gt region resident (rois/assign_gt may still fly)
    __syncthreads();

    // ---- GT preamble: one box per thread ----
    {
        const float* gp = sGTin + tid * 7;
        float cx = gp[0], cy = gp[1], cz = gp[2];
        float dx = gp[3], dy = gp[4], dz = gp[5];
        float h  = gp[6];
        float bmn[3] = { cx - 0.5f * dx, cy - 0.5f * dy, cz - 0.5f * dz };
        float bmx[3] = { cx + 0.5f * dx, cy + 0.5f * dy, cz + 0.5f * dz };
        sMin[tid] = make_float4(bmn[0], bmn[1], bmn[2], dx * dy * dz);
        sMax[tid] = make_float4(bmx[0], bmx[1], bmx[2], 0.f);
        sBox[tid][0] = cx; sBox[tid][1] = cy; sBox[tid][2] = cz;
        sBox[tid][3] = dx; sBox[tid][4] = dy; sBox[tid][5] = dz;
        sBox[tid][6] = -h;  // heading multiplied by -1 per reference
        sBox[tid][7] = __int_as_float(gt_lab[(size_t)batch * G + tid]);

        const unsigned bit = 1u << (tid & 31);
        const int w = tid >> 5;
        #pragma unroll
        for (int a = 0; a < 3; ++a) {
            const int ka = bidx(bmn[a] - MARGIN);
            const int kb = bidx(bmx[a] + MARGIN);
            for (int k = ka; k <= kb; ++k)
                atomicOr(((unsigned*)&sMsk[a][k]) + w, bit);
        }
    }
    cpa_wait<0>();       // rois/assign_gt resident
    __syncthreads();

    // ---- My ROI from staged sRO (conflict-free stride-7 LDS) ----
    const float r0 = sRO[tid * 7 + 0], r1 = sRO[tid * 7 + 1], r2 = sRO[tid * 7 + 2];
    const float r3 = sRO[tid * 7 + 3], r4 = sRO[tid * 7 + 4], r5 = sRO[tid * 7 + 5];

    const float aminx = r0 - 0.5f * r3, amaxx = r0 + 0.5f * r3;
    const float aminy = r1 - 0.5f * r4, amaxy = r1 + 0.5f * r4;
    const float aminz = r2 - 0.5f * r5, amaxz = r2 + 0.5f * r5;
    const float va = r3 * r4 * r5;

    const int alab = assign_lab[ri];    // coalesced 1 int/thread (prefetch early)

    // ---- Candidate mask: OR bucket masks per axis over ROI's bucket span,
    // then AND across axes. A box overlapping the ROI on axis a has its
    // interval intersecting the ROI interval, which lies within buckets
    // k0..k1 -> box present in the ORed mask. Margins dwarf fp rounding,
    // so the mask is conservative; zero-inter boxes can never win the
    // strict-'>' argmax, making the filter exactly lossless.
    unsigned cand[4];
    {
        const float lo[3] = { aminx - MARGIN, aminy - MARGIN, aminz - MARGIN };
        const float hi[3] = { amaxx + MARGIN, amaxy + MARGIN, amaxz + MARGIN };
        #pragma unroll
        for (int a = 0; a < 3; ++a) {
            const int k0 = bidx(lo[a]);
            const int k1 = bidx(hi[a]);
            uint4 m = sMsk[a][k0];
            for (int k = k0 + 1; k <= k1; ++k) {
                const uint4 mm = sMsk[a][k];
                m.x |= mm.x; m.y |= mm.y; m.z |= mm.z; m.w |= mm.w;
            }
            if (a == 0) { cand[0] = m.x; cand[1] = m.y; cand[2] = m.z; cand[3] = m.w; }
            else        { cand[0] &= m.x; cand[1] &= m.y; cand[2] &= m.z; cand[3] &= m.w; }
        }
    }

    // ---- Exact IoU-argmax over candidates (ascending g order) ----
    // iou = inter/(s - inter), s = va + vb, strictly monotone in inter/s
    // => argmax via cross-mult compare; strict '>' keeps first max (jnp.argmax).
    float bi = 0.f, bs = 1.f; int bg = 0;
    #pragma unroll
    for (int c = 0; c < 4; ++c) {
        unsigned m = cand[c];
        while (m) {
            const int b = __ffs(m) - 1;
            m &= m - 1;
            const int g = c * 32 + b;
            const float4 mn = sMin[g];
            const float4 mx = sMax[g];
            float ox = fminf(amaxx, mx.x) - fmaxf(aminx, mn.x);
            float oy = fminf(amaxy, mx.y) - fmaxf(aminy, mn.y);
            float oz = fminf(amaxz, mx.z) - fmaxf(aminz, mn.z);
            ox = fmaxf(ox, 0.0f);
            oy = fmaxf(oy, 0.0f);
            oz = fmaxf(oz, 0.0f);
            const float inter = ox * oy * oz;
            const float s     = va + mn.w;
            if (inter * bs > bi * s) { bi = inter; bs = s; bg = g; }
        }
    }

    // ---- rois passthrough store NOW (sRO stable since sync #2) to overlap
    // these STGs with the epilogue compute below ----
    {
        float4* orr = (float4*)(out + regionBase);
        #pragma unroll
        for (int i = tid; i < F4_ROWS; i += BLK)
            orr[i] = ((const float4*)sRO)[i];
    }

    const bool pos1 = (alab >= 0);
    // max_ov >= THRESH  <=>  bi >= THRESH * clip(s - bi, 1e-6)
    const bool pos2 = (!pos1) && (bi >= THRESH * fmaxf(bs - bi, 1e-6f));

    // ---- label & mask: direct coalesced per-thread stores ----
    {
        float* labBase  = out + (size_t)B * N * 14 + (size_t)batch * N + rowBase;
        float* maskBase = labBase + (size_t)B * N;
        int lab = pos1 ? alab : (pos2 ? __float_as_int(sBox[bg][7]) : NC);
        labBase[tid]  = (float)lab;
        maskBase[tid] = (pos1 || pos2) ? 1.0f : 0.0f;
    }

    // ---- Epilogue into staging (each thread writes only its own row) ----
    #pragma unroll
    for (int k = 0; k < 7; ++k) {
        float gv;
        if (pos1) {
            gv = sAG[tid * 7 + k];
            if (k == 6) gv = -gv;   // assign_gt heading negated per reference
        } else if (pos2) {
            gv = sBox[bg][k];       // heading already negated at store time
        } else {
            gv = 0.0f;              // must write: d_out is poisoned
        }
        sGO[tid * 7 + k] = gv;
    }
    __syncthreads();

    // ---- Cooperative coalesced store of gt_of_rois ----
    {
        float4* ogt = (float4*)(out + (size_t)B * N * 7 + regionBase);
        #pragma unroll
        for (int i = tid; i < F4_ROWS; i += BLK)
            ogt[i] = ((const float4*)sGO)[i];
    }
}

extern "C" void kernel_launch(void* const* d_in, const int* in_sizes, int n_in,
                              void* d_out, int out_size)
{
    const float* rois       = (const float*)d_in[0]; // [B,N,7]
    const float* gt         = (const float*)d_in[1]; // [B,G,7]
    const int*   gt_lab     = (const int*)  d_in[2]; // [B,G]
    const float* assign_gt  = (const float*)d_in[3]; // [B,N,7]
    const int*   assign_lab = (const int*)  d_in[4]; // [B,N]
    float*       out        = (float*)d_out;

    // 128 threads/block, 1 ROI/thread -> 1024 blocks
    ptl_kernel<<<(B * N) / BLK, BLK>>>(rois, gt, gt_lab, assign_gt, assign_lab, out);
}